// round 15
// baseline (speedup 1.0000x reference)
#include <cuda_runtime.h>
#include <cuda_fp16.h>
#include <math.h>
#include <stdint.h>

#define BATCH 8
#define SEQ   2048
#define KDIM  1024
#define LOWD  512

// ---------------------------------------------------------------------------
// Scratch (no cudaMalloc allowed)
// ---------------------------------------------------------------------------
__device__ __align__(1024) __half g_QKVh[3 * (size_t)BATCH * SEQ * KDIM]; // fp16 Q,K,V
__device__ __align__(1024) __half g_Wf [3 * (size_t)LOWD * KDIM];         // folded weights
__device__ __align__(1024) __half g_qkv[3 * (size_t)BATCH * SEQ * LOWD];  // q,k,v
__device__ __align__(1024) __half g_vT [(size_t)BATCH * SEQ * LOWD];      // v transposed
__device__ __align__(1024) float  g_P  [(size_t)BATCH * SEQ * SEQ];       // raw scores (fp32)
__device__ __align__(1024) __half g_Ph [(size_t)BATCH * SEQ * SEQ];       // probs (fp16)

// ---------------------------------------------------------------------------
// Helpers
// ---------------------------------------------------------------------------
__device__ __forceinline__ uint32_t tf32b(float x) {
    uint32_t u; asm("cvt.rna.tf32.f32 %0, %1;" : "=r"(u) : "f"(x)); return u;
}
__device__ __forceinline__ uint32_t smem_u32(const void* p) {
    uint32_t a;
    asm("{ .reg .u64 t; cvta.to.shared.u64 t, %1; cvt.u32.u64 %0, t; }" : "=r"(a) : "l"(p));
    return a;
}
__device__ __forceinline__ void cp16(void* s, const void* g) {
    unsigned sa = (unsigned)__cvta_generic_to_shared(s);
    asm volatile("cp.async.cg.shared.global [%0], [%1], 16;\n" :: "r"(sa), "l"(g));
}
__device__ __forceinline__ void cp_commit() { asm volatile("cp.async.commit_group;\n"); }
template<int NW> __device__ __forceinline__ void cp_wait() {
    asm volatile("cp.async.wait_group %0;\n" :: "n"(NW));
}
__device__ __forceinline__ void ldsm_x4(uint32_t* r, uint32_t addr) {
    asm volatile("ldmatrix.sync.aligned.m8n8.x4.shared.b16 {%0,%1,%2,%3}, [%4];"
        : "=r"(r[0]), "=r"(r[1]), "=r"(r[2]), "=r"(r[3]) : "r"(addr));
}
__device__ __forceinline__ void mma_f16(float* c, const uint32_t* a, uint32_t b0, uint32_t b1) {
    asm volatile(
        "mma.sync.aligned.m16n8k16.row.col.f32.f16.f16.f32 "
        "{%0,%1,%2,%3}, {%4,%5,%6,%7}, {%8,%9}, {%0,%1,%2,%3};"
        : "+f"(c[0]), "+f"(c[1]), "+f"(c[2]), "+f"(c[3])
        : "r"(a[0]), "r"(a[1]), "r"(a[2]), "r"(a[3]), "r"(b0), "r"(b1));
}

// ---------------------------------------------------------------------------
// fp32 -> fp16 conversion pass for Q/K/V (z selects source tensor).
// ---------------------------------------------------------------------------
__global__ void __launch_bounds__(256)
f2h_pass(const float* __restrict__ A0, const float* __restrict__ A1,
         const float* __restrict__ A2, __half* __restrict__ out)
{
    const int z = blockIdx.z;
    const float* src = (z == 1) ? A1 : ((z == 2) ? A2 : A0);
    __half* dst = out + (size_t)z * BATCH * SEQ * KDIM;
    const size_t i = ((size_t)blockIdx.x * 256 + threadIdx.x) * 8;
    float4 f0 = *(const float4*)(src + i);
    float4 f1 = *(const float4*)(src + i + 4);
    __half2 h[4];
    h[0] = __floats2half2_rn(f0.x, f0.y);
    h[1] = __floats2half2_rn(f0.z, f0.w);
    h[2] = __floats2half2_rn(f1.x, f1.y);
    h[3] = __floats2half2_rn(f1.z, f1.w);
    *(uint4*)(dst + i) = *(uint4*)h;
}

// ---------------------------------------------------------------------------
// Pure-fp16 NT GEMM: CTA tile 128(M) x 256(N), warp tile 64x64, BK=32.
// 3-stage cp.async pipeline (proven schedule), ldmatrix + XOR swizzle.
// 8 warps: wm = (warp&1)*64, wn = (warp>>1)*64.
// OUTH: write C fp16, else fp32. blockIdx.z batches via strides.
// Requires M%128==0, N%256==0, K%32==0, K/32 >= 2.
// ---------------------------------------------------------------------------
#define HG_ST     3
#define HG_ASZ    8192                     // A stage bytes: 128*32*2
#define HG_BSZ    16384                    // B stage bytes: 256*32*2
#define HG_SMEM   (HG_ST * (HG_ASZ + HG_BSZ))   // 73728

template<bool OUTH>
__global__ void __launch_bounds__(256, 1)
hgemm_nt(const __half* __restrict__ A_, const __half* __restrict__ B_, void* C_,
         int K, int ldA, int ldB, int ldC,
         long long sA, long long sB, long long sC, float alpha)
{
    extern __shared__ __align__(16) char smem[];
    __half* As = (__half*)smem;                           // [ST][128*32]
    __half* Bs = (__half*)(smem + HG_ST * HG_ASZ);        // [ST][256*32]

    const __half* Ap = A_ + (size_t)blockIdx.z * sA;
    const __half* Bp = B_ + (size_t)blockIdx.z * sB;
    float*  Cf = OUTH ? nullptr : ((float*)C_ + (size_t)blockIdx.z * sC);
    __half* Ch = OUTH ? ((__half*)C_ + (size_t)blockIdx.z * sC) : nullptr;

    const int tid  = threadIdx.x;
    const int lane = tid & 31;
    const int warp = tid >> 5;
    const int wm   = (warp & 1) * 64;    // 2 warps along M (128)
    const int wn   = (warp >> 1) * 64;   // 4 warps along N (256)
    const int m0   = blockIdx.y * 128;
    const int n0   = blockIdx.x * 256;

    // A staging: 128 rows, each thread owns one row-half (2 x 16B chunks)
    const int arow = tid >> 1;
    const int acc0 = (tid & 1) * 2;
    const int aswz = (arow >> 1) & 3;
    // B staging: 256 rows, each thread owns one full row (4 x 16B chunks)
    const int brow = tid;
    const int bswz = (brow >> 1) & 3;

    float acc[4][8][4];
    #pragma unroll
    for (int i = 0; i < 4; i++)
        #pragma unroll
        for (int j = 0; j < 8; j++)
            #pragma unroll
            for (int l = 0; l < 4; l++) acc[i][j][l] = 0.0f;

    const uint32_t As_u = smem_u32(As);
    const uint32_t Bs_u = smem_u32(Bs);
    const int KT = K / 32;

    auto stage_in = [&](int st, int k0) {
        const __half* pa = Ap + (size_t)(m0 + arow) * ldA + k0 + acc0 * 8;
        __half* sa = As + st * 4096 + arow * 32;
        cp16(sa + (((acc0    ) ^ aswz) << 3), pa);
        cp16(sa + (((acc0 + 1) ^ aswz) << 3), pa + 8);
        const __half* pb = Bp + (size_t)(n0 + brow) * ldB + k0;
        __half* sb = Bs + st * 8192 + brow * 32;
        #pragma unroll
        for (int c = 0; c < 4; c++)
            cp16(sb + ((c ^ bswz) << 3), pb + c * 8);
        cp_commit();
    };

    stage_in(0, 0);
    stage_in(1, 32);

    int cbuf = 0;
    for (int kt = 0; kt < KT; kt++) {
        cp_wait<HG_ST - 2>();   // tile kt resident
        __syncthreads();        // everyone done computing tile kt-1

        if (kt + 2 < KT) {
            int st = cbuf - 1; if (st < 0) st += HG_ST;
            stage_in(st, (kt + 2) * 32);
        } else {
            cp_commit();        // keep group accounting uniform
        }

        const uint32_t Ab = As_u + cbuf * HG_ASZ;
        const uint32_t Bb = Bs_u + cbuf * HG_BSZ;
        const int frow  = lane & 15;
        const int khalf = lane >> 4;
        #pragma unroll
        for (int ks = 0; ks < 2; ks++) {
            uint32_t a[4][4];
            #pragma unroll
            for (int mi = 0; mi < 4; mi++) {
                const int r  = wm + mi * 16 + frow;
                const int ch = (ks * 2 + khalf) ^ ((r >> 1) & 3);
                ldsm_x4(a[mi], Ab + r * 64 + ch * 16);
            }
            #pragma unroll
            for (int bj = 0; bj < 4; bj++) {
                const int r  = wn + bj * 16 + frow;
                const int ch = (ks * 2 + khalf) ^ ((r >> 1) & 3);
                uint32_t t[4];
                ldsm_x4(t, Bb + r * 64 + ch * 16);
                #pragma unroll
                for (int mi = 0; mi < 4; mi++) {
                    mma_f16(acc[mi][2 * bj],     a[mi], t[0], t[2]);
                    mma_f16(acc[mi][2 * bj + 1], a[mi], t[1], t[3]);
                }
            }
        }
        if (++cbuf == HG_ST) cbuf = 0;
    }

    // epilogue
    const int er = lane >> 2;
    const int ec = (lane & 3) * 2;
    #pragma unroll
    for (int mi = 0; mi < 4; mi++) {
        #pragma unroll
        for (int nj = 0; nj < 8; nj++) {
            const int r = m0 + wm + mi * 16 + er;
            const int c = n0 + wn + nj * 8 + ec;
            float v0 = acc[mi][nj][0] * alpha, v1 = acc[mi][nj][1] * alpha;
            float v2 = acc[mi][nj][2] * alpha, v3 = acc[mi][nj][3] * alpha;
            if (OUTH) {
                *(__half2*)(Ch + (size_t)r * ldC + c)       = __floats2half2_rn(v0, v1);
                *(__half2*)(Ch + (size_t)(r + 8) * ldC + c) = __floats2half2_rn(v2, v3);
            } else {
                *(float2*)(Cf + (size_t)r * ldC + c)        = make_float2(v0, v1);
                *(float2*)(Cf + (size_t)(r + 8) * ldC + c)  = make_float2(v2, v3);
            }
        }
    }
}

// ---------------------------------------------------------------------------
// Fused weight folds (tf32 mma, NN): Wf[z] = W{q,k,v} @ Wr, fp16 out.
// Single launch with z selecting the A operand (unchanged from R11 pass).
// ---------------------------------------------------------------------------
#define BKP 20
__device__ __forceinline__ void mma_m16n8k8(float* c, const uint32_t* a, const uint32_t* b) {
    asm volatile(
        "mma.sync.aligned.m16n8k8.row.col.f32.tf32.tf32.f32 "
        "{%0,%1,%2,%3}, {%4,%5,%6,%7}, {%8,%9}, {%0,%1,%2,%3};\n"
        : "+f"(c[0]), "+f"(c[1]), "+f"(c[2]), "+f"(c[3])
        : "r"(a[0]), "r"(a[1]), "r"(a[2]), "r"(a[3]), "r"(b[0]), "r"(b[1]));
}

__global__ void __launch_bounds__(256)
fold_nn(const float* __restrict__ A0, const float* __restrict__ A1,
        const float* __restrict__ A2, const float* __restrict__ B,
        __half* __restrict__ C_, int K, int ldA, int ldB, int ldC, long long sC)
{
    __shared__ float As[2][128][BKP];
    __shared__ float Bs[2][128][BKP];

    const int z = blockIdx.z;
    const float* A = (z == 1) ? A1 : ((z == 2) ? A2 : A0);
    __half* C = C_ + (size_t)z * sC;

    const int tid = threadIdx.x;
    const int lane = tid & 31;
    const int warp = tid >> 5;
    const int wm = (warp & 3) * 32;
    const int wn = (warp >> 2) * 64;
    const int m0 = blockIdx.y * 128;
    const int n0 = blockIdx.x * 128;

    const int lr = tid >> 1;
    const int lk = (tid & 1) * 8;
    const int bn = tid & 127;
    const int bk0 = (tid >> 7) * 8;

    float acc[2][8][4];
    #pragma unroll
    for (int i = 0; i < 2; i++)
        #pragma unroll
        for (int j = 0; j < 8; j++)
            #pragma unroll
            for (int l = 0; l < 4; l++) acc[i][j][l] = 0.0f;

    const int KT = K / 16;
    float regB[8];
    {
        const float* Ag = A + (size_t)(m0 + lr) * ldA + lk;
        cp16(&As[0][lr][lk], Ag);
        cp16(&As[0][lr][lk + 4], Ag + 4);
        #pragma unroll
        for (int j = 0; j < 8; j++) regB[j] = B[(size_t)(bk0 + j) * ldB + n0 + bn];
        cp_commit();
    }
    for (int kt = 0; kt < KT; kt++) {
        const int buf = kt & 1;
        #pragma unroll
        for (int j = 0; j < 8; j++) Bs[buf][bn][bk0 + j] = regB[j];
        if (kt + 1 < KT) {
            const int nb = (kt + 1) & 1;
            const int k0 = (kt + 1) * 16;
            const float* Ag = A + (size_t)(m0 + lr) * ldA + k0 + lk;
            cp16(&As[nb][lr][lk], Ag);
            cp16(&As[nb][lr][lk + 4], Ag + 4);
            #pragma unroll
            for (int j = 0; j < 8; j++) regB[j] = B[(size_t)(k0 + bk0 + j) * ldB + n0 + bn];
            cp_commit();
            cp_wait<1>();
        } else {
            cp_wait<0>();
        }
        __syncthreads();
        const int g = lane >> 2, tg = lane & 3;
        #pragma unroll
        for (int ks = 0; ks < 2; ks++) {
            const int kk = ks * 8;
            uint32_t a[2][4];
            #pragma unroll
            for (int mi = 0; mi < 2; mi++) {
                const int r = wm + mi * 16 + g;
                a[mi][0] = tf32b(As[buf][r][kk + tg]);
                a[mi][1] = tf32b(As[buf][r + 8][kk + tg]);
                a[mi][2] = tf32b(As[buf][r][kk + tg + 4]);
                a[mi][3] = tf32b(As[buf][r + 8][kk + tg + 4]);
            }
            #pragma unroll
            for (int ni = 0; ni < 8; ni++) {
                const int n = wn + ni * 8 + g;
                uint32_t b[2] = { tf32b(Bs[buf][n][kk + tg]), tf32b(Bs[buf][n][kk + tg + 4]) };
                mma_m16n8k8(acc[0][ni], a[0], b);
                mma_m16n8k8(acc[1][ni], a[1], b);
            }
        }
        __syncthreads();
    }
    const int g = lane >> 2, tg = lane & 3;
    #pragma unroll
    for (int mi = 0; mi < 2; mi++)
        #pragma unroll
        for (int ni = 0; ni < 8; ni++) {
            const int r = m0 + wm + mi * 16 + g;
            const int c = n0 + wn + ni * 8 + tg * 2;
            *(__half2*)(C + (size_t)r * ldC + c) =
                __floats2half2_rn(acc[mi][ni][0], acc[mi][ni][1]);
            *(__half2*)(C + (size_t)(r + 8) * ldC + c) =
                __floats2half2_rn(acc[mi][ni][2], acc[mi][ni][3]);
        }
}

// ---------------------------------------------------------------------------
// v [b][s][e] -> vT [b][e][s] (fp16, 32x32 smem tiles)
// ---------------------------------------------------------------------------
__global__ void __launch_bounds__(256)
transpose_v(const __half* __restrict__ in, __half* __restrict__ out)
{
    __shared__ __half t[32][33];
    const __half* bi = in  + (size_t)blockIdx.z * SEQ * LOWD;
    __half*       bo = out + (size_t)blockIdx.z * SEQ * LOWD;
    const int x0 = blockIdx.x * 32;
    const int y0 = blockIdx.y * 32;
    const int tx = threadIdx.x, ty = threadIdx.y;
    #pragma unroll
    for (int i = ty; i < 32; i += 8)
        t[i][tx] = bi[(size_t)(y0 + i) * LOWD + x0 + tx];
    __syncthreads();
    #pragma unroll
    for (int i = ty; i < 32; i += 8)
        bo[(size_t)(x0 + i) * SEQ + y0 + tx] = t[tx][i];
}

// ---------------------------------------------------------------------------
// Softmax: rows of 2048 fp32 scores -> fp16 probs. Single pass, regs-resident.
// ---------------------------------------------------------------------------
__global__ void __launch_bounds__(256)
softmax_h(const float* __restrict__ P, __half* __restrict__ Ph)
{
    const size_t off = (size_t)blockIdx.x * SEQ;
    const float* row = P + off;
    __half* orow = Ph + off;
    const int t = threadIdx.x;
    const int lane = t & 31, warp = t >> 5;

    float v[8];
    {
        float4 f0 = *(const float4*)(row + t * 8);
        float4 f1 = *(const float4*)(row + t * 8 + 4);
        v[0] = f0.x; v[1] = f0.y; v[2] = f0.z; v[3] = f0.w;
        v[4] = f1.x; v[5] = f1.y; v[6] = f1.z; v[7] = f1.w;
    }
    float m = v[0];
    #pragma unroll
    for (int i = 1; i < 8; i++) m = fmaxf(m, v[i]);
    #pragma unroll
    for (int o = 16; o; o >>= 1) m = fmaxf(m, __shfl_xor_sync(0xffffffffu, m, o));
    __shared__ float redm[8], reds[8];
    if (lane == 0) redm[warp] = m;
    __syncthreads();
    float gm = redm[0];
    #pragma unroll
    for (int i = 1; i < 8; i++) gm = fmaxf(gm, redm[i]);

    float s = 0.0f;
    #pragma unroll
    for (int i = 0; i < 8; i++) { v[i] = __expf(v[i] - gm); s += v[i]; }
    #pragma unroll
    for (int o = 16; o; o >>= 1) s += __shfl_xor_sync(0xffffffffu, s, o);
    if (lane == 0) reds[warp] = s;
    __syncthreads();
    float gs = 0.0f;
    #pragma unroll
    for (int i = 0; i < 8; i++) gs += reds[i];
    const float inv = 1.0f / gs;

    __half2 h[4];
    #pragma unroll
    for (int j = 0; j < 4; j++)
        h[j] = __floats2half2_rn(v[2 * j] * inv, v[2 * j + 1] * inv);
    *(uint4*)(orow + t * 8) = *(uint4*)h;
}

// ---------------------------------------------------------------------------
// Launch sequence (graph-capturable; no sync, no alloc)
// ---------------------------------------------------------------------------
extern "C" void kernel_launch(void* const* d_in, const int* in_sizes, int n_in,
                              void* d_out, int out_size)
{
    const float* Q  = (const float*)d_in[0];
    const float* K  = (const float*)d_in[1];
    const float* V  = (const float*)d_in[2];
    const float* Wr = (const float*)d_in[3];
    const float* Wq = (const float*)d_in[4];
    const float* Wk = (const float*)d_in[5];
    const float* Wv = (const float*)d_in[6];
    float* out = (float*)d_out;

    __half *pQKVh, *pWf, *pqkv, *pvT, *pPh;
    float* pP;
    cudaGetSymbolAddress((void**)&pQKVh, g_QKVh);
    cudaGetSymbolAddress((void**)&pWf,   g_Wf);
    cudaGetSymbolAddress((void**)&pqkv,  g_qkv);
    cudaGetSymbolAddress((void**)&pvT,   g_vT);
    cudaGetSymbolAddress((void**)&pP,    g_P);
    cudaGetSymbolAddress((void**)&pPh,   g_Ph);

    cudaFuncSetAttribute((const void*)hgemm_nt<true>,
                         cudaFuncAttributeMaxDynamicSharedMemorySize, HG_SMEM);
    cudaFuncSetAttribute((const void*)hgemm_nt<false>,
                         cudaFuncAttributeMaxDynamicSharedMemorySize, HG_SMEM);

    const long long sIN = (long long)BATCH * SEQ * KDIM;   // fp16 Q/K/V stride
    const long long sW  = (long long)LOWD * KDIM;
    const long long sQK = (long long)BATCH * SEQ * LOWD;   // q/k/v stride in g_qkv
    const long long sBS = (long long)SEQ * LOWD;           // per-batch q/k/v stride
    const float scale = 1.0f / sqrtf((float)LOWD);

    // 0) Convert Q,K,V fp32 -> fp16
    {
        dim3 grid((unsigned)(sIN / (256 * 8)), 1, 3);
        f2h_pass<<<grid, 256>>>(Q, K, V, pQKVh);
    }

    // 1) Fold weights (single fused launch over z): Wf[z] = W{q,k,v} @ Wr
    {
        dim3 grid(KDIM / 128, LOWD / 128, 3);
        fold_nn<<<grid, 256>>>(Wq, Wk, Wv, Wr, pWf, LOWD, LOWD, KDIM, KDIM, sW);
    }

    // 2) Projections (fused over z): qkv[z] = QKVh[z] @ Wf[z]^T  (fp16 out)
    {
        dim3 grid(LOWD / 256, (BATCH * SEQ) / 128, 3);
        hgemm_nt<true><<<grid, 256, HG_SMEM>>>(
            pQKVh, pWf, pqkv, KDIM, KDIM, KDIM, LOWD, sIN, sW, sQK, 1.0f);
    }

    // 3) vT for the NT AV GEMM
    {
        dim3 grid(LOWD / 32, SEQ / 32, BATCH);
        transpose_v<<<grid, dim3(32, 8)>>>(pqkv + 2 * sQK, pvT);
    }

    // 4) Scores: P[b] = scale * q[b] @ k[b]^T  (fp32 out)
    {
        dim3 grid(SEQ / 256, SEQ / 128, BATCH);
        hgemm_nt<false><<<grid, 256, HG_SMEM>>>(
            pqkv, pqkv + sQK, pP, LOWD, LOWD, LOWD, SEQ,
            sBS, sBS, (long long)SEQ * SEQ, scale);
    }

    // 5) Softmax: fp32 scores -> fp16 probs
    softmax_h<<<BATCH * SEQ, 256>>>(pP, pPh);

    // 6) AV: out[b] = Ph[b] @ vT[b]^T  (fp32 out)
    {
        dim3 grid(LOWD / 256, SEQ / 128, BATCH);
        hgemm_nt<false><<<grid, 256, HG_SMEM>>>(
            pPh, pvT, out, SEQ, SEQ, SEQ, LOWD,
            (long long)SEQ * SEQ, sBS, sBS, 1.0f);
    }
}

// round 16
// speedup vs baseline: 1.2955x; 1.2955x over previous
#include <cuda_runtime.h>
#include <cuda_fp16.h>
#include <math.h>
#include <stdint.h>

#define BATCH 8
#define SEQ   2048
#define KDIM  1024
#define LOWD  512

// ---------------------------------------------------------------------------
// Scratch (no cudaMalloc allowed)
// ---------------------------------------------------------------------------
__device__ __align__(1024) __half g_Wf [3 * (size_t)LOWD * KDIM];         // folded weights
__device__ __align__(1024) __half g_qkv[3 * (size_t)BATCH * SEQ * LOWD];  // q,k,v
__device__ __align__(1024) __half g_vT [(size_t)BATCH * SEQ * LOWD];      // v transposed
__device__ __align__(1024) float  g_P  [(size_t)BATCH * SEQ * SEQ];       // raw scores (fp32)
__device__ __align__(1024) __half g_Ph [(size_t)BATCH * SEQ * SEQ];       // probs (fp16)

// ---------------------------------------------------------------------------
// Helpers
// ---------------------------------------------------------------------------
__device__ __forceinline__ uint32_t tf32b(float x) {
    uint32_t u; asm("cvt.rna.tf32.f32 %0, %1;" : "=r"(u) : "f"(x)); return u;
}
__device__ __forceinline__ uint32_t smem_u32(const void* p) {
    uint32_t a;
    asm("{ .reg .u64 t; cvta.to.shared.u64 t, %1; cvt.u32.u64 %0, t; }" : "=r"(a) : "l"(p));
    return a;
}
__device__ __forceinline__ void cp16(void* s, const void* g) {
    unsigned sa = (unsigned)__cvta_generic_to_shared(s);
    asm volatile("cp.async.cg.shared.global [%0], [%1], 16;\n" :: "r"(sa), "l"(g));
}
__device__ __forceinline__ void cp_commit() { asm volatile("cp.async.commit_group;\n"); }
template<int NW> __device__ __forceinline__ void cp_wait() {
    asm volatile("cp.async.wait_group %0;\n" :: "n"(NW));
}
__device__ __forceinline__ void ldsm_x4(uint32_t* r, uint32_t addr) {
    asm volatile("ldmatrix.sync.aligned.m8n8.x4.shared.b16 {%0,%1,%2,%3}, [%4];"
        : "=r"(r[0]), "=r"(r[1]), "=r"(r[2]), "=r"(r[3]) : "r"(addr));
}
__device__ __forceinline__ void mma_f16(float* c, const uint32_t* a, uint32_t b0, uint32_t b1) {
    asm volatile(
        "mma.sync.aligned.m16n8k16.row.col.f32.f16.f16.f32 "
        "{%0,%1,%2,%3}, {%4,%5,%6,%7}, {%8,%9}, {%0,%1,%2,%3};"
        : "+f"(c[0]), "+f"(c[1]), "+f"(c[2]), "+f"(c[3])
        : "r"(a[0]), "r"(a[1]), "r"(a[2]), "r"(a[3]), "r"(b0), "r"(b1));
}
__device__ __forceinline__ uint32_t f2h2(float lo, float hi) {
    __half2 h = __floats2half2_rn(lo, hi);
    return *(uint32_t*)&h;
}

// ---------------------------------------------------------------------------
// Pure-fp16 NT GEMM with 3-stage cp.async pipeline (proven R11 kernel).
// C[m][n] = alpha * sum_k A[m][k] * B[n][k];  BM=BN=128, BK=32.
// 8 warps (4x2), warp tile 32x64, ldmatrix + XOR swizzle.
// OUTH: write C fp16, else fp32. blockIdx.z batches via strides.
// ---------------------------------------------------------------------------
template<bool OUTH>
__global__ void __launch_bounds__(256, 2)
hgemm_nt(const __half* __restrict__ A_, const __half* __restrict__ B_, void* C_,
         int K, int ldA, int ldB, int ldC,
         long long sA, long long sB, long long sC, float alpha)
{
    constexpr int ST = 3;
    __shared__ __align__(16) __half As[ST][128 * 32];
    __shared__ __align__(16) __half Bs[ST][128 * 32];

    const __half* Ap = A_ + (size_t)blockIdx.z * sA;
    const __half* Bp = B_ + (size_t)blockIdx.z * sB;
    float*  Cf = OUTH ? nullptr : ((float*)C_ + (size_t)blockIdx.z * sC);
    __half* Ch = OUTH ? ((__half*)C_ + (size_t)blockIdx.z * sC) : nullptr;

    const int tid  = threadIdx.x;
    const int lane = tid & 31;
    const int warp = tid >> 5;
    const int wm   = (warp & 3) * 32;
    const int wn   = (warp >> 2) * 64;
    const int m0   = blockIdx.y * 128;
    const int n0   = blockIdx.x * 128;

    const int srow = tid >> 1;
    const int cc   = (tid & 1) * 2;
    const int ssw  = (srow >> 1) & 3;

    float acc[2][8][4];
    #pragma unroll
    for (int i = 0; i < 2; i++)
        #pragma unroll
        for (int j = 0; j < 8; j++)
            #pragma unroll
            for (int l = 0; l < 4; l++) acc[i][j][l] = 0.0f;

    const uint32_t As_u = smem_u32(As);
    const uint32_t Bs_u = smem_u32(Bs);
    const int KT = K / 32;

    auto stage_in = [&](int st, int k0) {
        const __half* pa = Ap + (size_t)(m0 + srow) * ldA + k0 + cc * 8;
        cp16(&As[st][srow * 32 + ((cc       ^ ssw) << 3)], pa);
        cp16(&As[st][srow * 32 + (((cc + 1) ^ ssw) << 3)], pa + 8);
        const __half* pb = Bp + (size_t)(n0 + srow) * ldB + k0 + cc * 8;
        cp16(&Bs[st][srow * 32 + ((cc       ^ ssw) << 3)], pb);
        cp16(&Bs[st][srow * 32 + (((cc + 1) ^ ssw) << 3)], pb + 8);
        cp_commit();
    };

    stage_in(0, 0);
    stage_in(1, 32);

    int cbuf = 0;
    for (int kt = 0; kt < KT; kt++) {
        cp_wait<ST - 2>();
        __syncthreads();

        if (kt + 2 < KT) {
            int st = cbuf - 1; if (st < 0) st += ST;
            stage_in(st, (kt + 2) * 32);
        } else {
            cp_commit();
        }

        const uint32_t Ab = As_u + cbuf * 8192;
        const uint32_t Bb = Bs_u + cbuf * 8192;
        const int frow  = lane & 15;
        const int khalf = lane >> 4;
        #pragma unroll
        for (int ks = 0; ks < 2; ks++) {
            uint32_t a[2][4];
            #pragma unroll
            for (int mi = 0; mi < 2; mi++) {
                const int r  = wm + mi * 16 + frow;
                const int ch = (ks * 2 + khalf) ^ ((r >> 1) & 3);
                ldsm_x4(a[mi], Ab + r * 64 + ch * 16);
            }
            #pragma unroll
            for (int bj = 0; bj < 4; bj++) {
                const int r  = wn + bj * 16 + frow;
                const int ch = (ks * 2 + khalf) ^ ((r >> 1) & 3);
                uint32_t t[4];
                ldsm_x4(t, Bb + r * 64 + ch * 16);
                mma_f16(acc[0][2 * bj],     a[0], t[0], t[2]);
                mma_f16(acc[1][2 * bj],     a[1], t[0], t[2]);
                mma_f16(acc[0][2 * bj + 1], a[0], t[1], t[3]);
                mma_f16(acc[1][2 * bj + 1], a[1], t[1], t[3]);
            }
        }
        if (++cbuf == ST) cbuf = 0;
    }

    const int er = lane >> 2;
    const int ec = (lane & 3) * 2;
    #pragma unroll
    for (int mi = 0; mi < 2; mi++) {
        #pragma unroll
        for (int nj = 0; nj < 8; nj++) {
            const int r = m0 + wm + mi * 16 + er;
            const int c = n0 + wn + nj * 8 + ec;
            float v0 = acc[mi][nj][0] * alpha, v1 = acc[mi][nj][1] * alpha;
            float v2 = acc[mi][nj][2] * alpha, v3 = acc[mi][nj][3] * alpha;
            if (OUTH) {
                *(__half2*)(Ch + (size_t)r * ldC + c)       = __floats2half2_rn(v0, v1);
                *(__half2*)(Ch + (size_t)(r + 8) * ldC + c) = __floats2half2_rn(v2, v3);
            } else {
                *(float2*)(Cf + (size_t)r * ldC + c)        = make_float2(v0, v1);
                *(float2*)(Cf + (size_t)(r + 8) * ldC + c)  = make_float2(v2, v3);
            }
        }
    }
}

// ---------------------------------------------------------------------------
// Projection GEMM: A = fp32 (Q/K/V selected by z), converted rn to fp16 while
// staging via the register-prefetch path (R5-proven); B = fp16 weights via
// 3-stage cp.async (R11-proven). C fp16.  qkv[z] = rn16(QKV[z]) @ Wf[z]^T.
// A double-buffered (2 smem stages), B triple-buffered.
// ---------------------------------------------------------------------------
__global__ void __launch_bounds__(256, 2)
hgemm_proj(const float* __restrict__ A0, const float* __restrict__ A1,
           const float* __restrict__ A2, const __half* __restrict__ B_,
           __half* __restrict__ C_, long long sB, long long sC)
{
    __shared__ __align__(16) __half As[2][128 * 32];   // 16 KB
    __shared__ __align__(16) __half Bs[3][128 * 32];   // 24 KB

    const int z = blockIdx.z;
    const float* Ap = (z == 1) ? A1 : ((z == 2) ? A2 : A0);
    const __half* Bp = B_ + (size_t)z * sB;
    __half* Ch = C_ + (size_t)z * sC;

    const int tid  = threadIdx.x;
    const int lane = tid & 31;
    const int warp = tid >> 5;
    const int wm   = (warp & 3) * 32;
    const int wn   = (warp >> 2) * 64;
    const int m0   = blockIdx.y * 128;
    const int n0   = blockIdx.x * 128;

    const int srow = tid >> 1;
    const int cc   = (tid & 1) * 2;
    const int ssw  = (srow >> 1) & 3;

    float acc[2][8][4];
    #pragma unroll
    for (int i = 0; i < 2; i++)
        #pragma unroll
        for (int j = 0; j < 8; j++)
            #pragma unroll
            for (int l = 0; l < 4; l++) acc[i][j][l] = 0.0f;

    const uint32_t As_u = smem_u32(As);
    const uint32_t Bs_u = smem_u32(Bs);
    const int KT = KDIM / 32;   // 32

    auto stageB = [&](int st, int k0) {
        const __half* pb = Bp + (size_t)(n0 + srow) * KDIM + k0 + cc * 8;
        cp16(&Bs[st][srow * 32 + ((cc       ^ ssw) << 3)], pb);
        cp16(&Bs[st][srow * 32 + (((cc + 1) ^ ssw) << 3)], pb + 8);
        cp_commit();
    };
    auto loadA = [&](int k0, float4* f) {
        const float* p = Ap + (size_t)(m0 + srow) * KDIM + k0 + cc * 8;
        f[0] = *(const float4*)(p);
        f[1] = *(const float4*)(p + 4);
        f[2] = *(const float4*)(p + 8);
        f[3] = *(const float4*)(p + 12);
    };

    float4 fA[4];
    loadA(0, fA);
    stageB(0, 0);
    stageB(1, 32);

    for (int kt = 0; kt < KT; kt++) {
        const int abuf = kt & 1;
        // convert + swizzled STS of A tile kt (readers of As[abuf] finished
        // in compute(kt-2), before sync(kt-1) which precedes this point)
        {
            uint4 c0 = make_uint4(f2h2(fA[0].x, fA[0].y), f2h2(fA[0].z, fA[0].w),
                                  f2h2(fA[1].x, fA[1].y), f2h2(fA[1].z, fA[1].w));
            uint4 c1 = make_uint4(f2h2(fA[2].x, fA[2].y), f2h2(fA[2].z, fA[2].w),
                                  f2h2(fA[3].x, fA[3].y), f2h2(fA[3].z, fA[3].w));
            *(uint4*)&As[abuf][srow * 32 + ((cc       ^ ssw) << 3)] = c0;
            *(uint4*)&As[abuf][srow * 32 + (((cc + 1) ^ ssw) << 3)] = c1;
        }
        if (kt + 1 < KT) loadA((kt + 1) * 32, fA);   // reg prefetch next A

        cp_wait<1>();           // B tile kt resident
        __syncthreads();        // orders A STS for ldsm; all done compute(kt-1)

        if (kt + 2 < KT) stageB((kt + 2) % 3, (kt + 2) * 32);
        else             cp_commit();   // uniform group accounting

        const uint32_t Ab = As_u + abuf * 8192;
        const uint32_t Bb = Bs_u + (kt % 3) * 8192;
        const int frow  = lane & 15;
        const int khalf = lane >> 4;
        #pragma unroll
        for (int ks = 0; ks < 2; ks++) {
            uint32_t a[2][4];
            #pragma unroll
            for (int mi = 0; mi < 2; mi++) {
                const int r  = wm + mi * 16 + frow;
                const int ch = (ks * 2 + khalf) ^ ((r >> 1) & 3);
                ldsm_x4(a[mi], Ab + r * 64 + ch * 16);
            }
            #pragma unroll
            for (int bj = 0; bj < 4; bj++) {
                const int r  = wn + bj * 16 + frow;
                const int ch = (ks * 2 + khalf) ^ ((r >> 1) & 3);
                uint32_t t[4];
                ldsm_x4(t, Bb + r * 64 + ch * 16);
                mma_f16(acc[0][2 * bj],     a[0], t[0], t[2]);
                mma_f16(acc[1][2 * bj],     a[1], t[0], t[2]);
                mma_f16(acc[0][2 * bj + 1], a[0], t[1], t[3]);
                mma_f16(acc[1][2 * bj + 1], a[1], t[1], t[3]);
            }
        }
    }

    const int er = lane >> 2;
    const int ec = (lane & 3) * 2;
    #pragma unroll
    for (int mi = 0; mi < 2; mi++) {
        #pragma unroll
        for (int nj = 0; nj < 8; nj++) {
            const int r = m0 + wm + mi * 16 + er;
            const int c = n0 + wn + nj * 8 + ec;
            *(__half2*)(Ch + (size_t)r * LOWD + c) =
                __floats2half2_rn(acc[mi][nj][0], acc[mi][nj][1]);
            *(__half2*)(Ch + (size_t)(r + 8) * LOWD + c) =
                __floats2half2_rn(acc[mi][nj][2], acc[mi][nj][3]);
        }
    }
}

// ---------------------------------------------------------------------------
// Fused weight folds (tf32 mma, NN): Wf[z] = W{q,k,v} @ Wr, fp16 out.
// ---------------------------------------------------------------------------
#define BKP 20
__device__ __forceinline__ void mma_m16n8k8(float* c, const uint32_t* a, const uint32_t* b) {
    asm volatile(
        "mma.sync.aligned.m16n8k8.row.col.f32.tf32.tf32.f32 "
        "{%0,%1,%2,%3}, {%4,%5,%6,%7}, {%8,%9}, {%0,%1,%2,%3};\n"
        : "+f"(c[0]), "+f"(c[1]), "+f"(c[2]), "+f"(c[3])
        : "r"(a[0]), "r"(a[1]), "r"(a[2]), "r"(a[3]), "r"(b[0]), "r"(b[1]));
}

__global__ void __launch_bounds__(256)
fold_nn(const float* __restrict__ A0, const float* __restrict__ A1,
        const float* __restrict__ A2, const float* __restrict__ B,
        __half* __restrict__ C_, int K, int ldA, int ldB, int ldC, long long sC)
{
    __shared__ float As[2][128][BKP];
    __shared__ float Bs[2][128][BKP];

    const int z = blockIdx.z;
    const float* A = (z == 1) ? A1 : ((z == 2) ? A2 : A0);
    __half* C = C_ + (size_t)z * sC;

    const int tid = threadIdx.x;
    const int lane = tid & 31;
    const int warp = tid >> 5;
    const int wm = (warp & 3) * 32;
    const int wn = (warp >> 2) * 64;
    const int m0 = blockIdx.y * 128;
    const int n0 = blockIdx.x * 128;

    const int lr = tid >> 1;
    const int lk = (tid & 1) * 8;
    const int bn = tid & 127;
    const int bk0 = (tid >> 7) * 8;

    float acc[2][8][4];
    #pragma unroll
    for (int i = 0; i < 2; i++)
        #pragma unroll
        for (int j = 0; j < 8; j++)
            #pragma unroll
            for (int l = 0; l < 4; l++) acc[i][j][l] = 0.0f;

    const int KT = K / 16;
    float regB[8];
    {
        const float* Ag = A + (size_t)(m0 + lr) * ldA + lk;
        cp16(&As[0][lr][lk], Ag);
        cp16(&As[0][lr][lk + 4], Ag + 4);
        #pragma unroll
        for (int j = 0; j < 8; j++) regB[j] = B[(size_t)(bk0 + j) * ldB + n0 + bn];
        cp_commit();
    }
    for (int kt = 0; kt < KT; kt++) {
        const int buf = kt & 1;
        #pragma unroll
        for (int j = 0; j < 8; j++) Bs[buf][bn][bk0 + j] = regB[j];
        if (kt + 1 < KT) {
            const int nb = (kt + 1) & 1;
            const int k0 = (kt + 1) * 16;
            const float* Ag = A + (size_t)(m0 + lr) * ldA + k0 + lk;
            cp16(&As[nb][lr][lk], Ag);
            cp16(&As[nb][lr][lk + 4], Ag + 4);
            #pragma unroll
            for (int j = 0; j < 8; j++) regB[j] = B[(size_t)(k0 + bk0 + j) * ldB + n0 + bn];
            cp_commit();
            cp_wait<1>();
        } else {
            cp_wait<0>();
        }
        __syncthreads();
        const int g = lane >> 2, tg = lane & 3;
        #pragma unroll
        for (int ks = 0; ks < 2; ks++) {
            const int kk = ks * 8;
            uint32_t a[2][4];
            #pragma unroll
            for (int mi = 0; mi < 2; mi++) {
                const int r = wm + mi * 16 + g;
                a[mi][0] = tf32b(As[buf][r][kk + tg]);
                a[mi][1] = tf32b(As[buf][r + 8][kk + tg]);
                a[mi][2] = tf32b(As[buf][r][kk + tg + 4]);
                a[mi][3] = tf32b(As[buf][r + 8][kk + tg + 4]);
            }
            #pragma unroll
            for (int ni = 0; ni < 8; ni++) {
                const int n = wn + ni * 8 + g;
                uint32_t b[2] = { tf32b(Bs[buf][n][kk + tg]), tf32b(Bs[buf][n][kk + tg + 4]) };
                mma_m16n8k8(acc[0][ni], a[0], b);
                mma_m16n8k8(acc[1][ni], a[1], b);
            }
        }
        __syncthreads();
    }
    const int g = lane >> 2, tg = lane & 3;
    #pragma unroll
    for (int mi = 0; mi < 2; mi++)
        #pragma unroll
        for (int ni = 0; ni < 8; ni++) {
            const int r = m0 + wm + mi * 16 + g;
            const int c = n0 + wn + ni * 8 + tg * 2;
            *(__half2*)(C + (size_t)r * ldC + c) =
                __floats2half2_rn(acc[mi][ni][0], acc[mi][ni][1]);
            *(__half2*)(C + (size_t)(r + 8) * ldC + c) =
                __floats2half2_rn(acc[mi][ni][2], acc[mi][ni][3]);
        }
}

// ---------------------------------------------------------------------------
// v [b][s][e] -> vT [b][e][s] (fp16, 32x32 smem tiles)
// ---------------------------------------------------------------------------
__global__ void __launch_bounds__(256)
transpose_v(const __half* __restrict__ in, __half* __restrict__ out)
{
    __shared__ __half t[32][33];
    const __half* bi = in  + (size_t)blockIdx.z * SEQ * LOWD;
    __half*       bo = out + (size_t)blockIdx.z * SEQ * LOWD;
    const int x0 = blockIdx.x * 32;
    const int y0 = blockIdx.y * 32;
    const int tx = threadIdx.x, ty = threadIdx.y;
    #pragma unroll
    for (int i = ty; i < 32; i += 8)
        t[i][tx] = bi[(size_t)(y0 + i) * LOWD + x0 + tx];
    __syncthreads();
    #pragma unroll
    for (int i = ty; i < 32; i += 8)
        bo[(size_t)(x0 + i) * SEQ + y0 + tx] = t[tx][i];
}

// ---------------------------------------------------------------------------
// Softmax: rows of 2048 fp32 scores -> fp16 probs. Single pass, regs-resident.
// ---------------------------------------------------------------------------
__global__ void __launch_bounds__(256)
softmax_h(const float* __restrict__ P, __half* __restrict__ Ph)
{
    const size_t off = (size_t)blockIdx.x * SEQ;
    const float* row = P + off;
    __half* orow = Ph + off;
    const int t = threadIdx.x;
    const int lane = t & 31, warp = t >> 5;

    float v[8];
    {
        float4 f0 = *(const float4*)(row + t * 8);
        float4 f1 = *(const float4*)(row + t * 8 + 4);
        v[0] = f0.x; v[1] = f0.y; v[2] = f0.z; v[3] = f0.w;
        v[4] = f1.x; v[5] = f1.y; v[6] = f1.z; v[7] = f1.w;
    }
    float m = v[0];
    #pragma unroll
    for (int i = 1; i < 8; i++) m = fmaxf(m, v[i]);
    #pragma unroll
    for (int o = 16; o; o >>= 1) m = fmaxf(m, __shfl_xor_sync(0xffffffffu, m, o));
    __shared__ float redm[8], reds[8];
    if (lane == 0) redm[warp] = m;
    __syncthreads();
    float gm = redm[0];
    #pragma unroll
    for (int i = 1; i < 8; i++) gm = fmaxf(gm, redm[i]);

    float s = 0.0f;
    #pragma unroll
    for (int i = 0; i < 8; i++) { v[i] = __expf(v[i] - gm); s += v[i]; }
    #pragma unroll
    for (int o = 16; o; o >>= 1) s += __shfl_xor_sync(0xffffffffu, s, o);
    if (lane == 0) reds[warp] = s;
    __syncthreads();
    float gs = 0.0f;
    #pragma unroll
    for (int i = 0; i < 8; i++) gs += reds[i];
    const float inv = 1.0f / gs;

    __half2 h[4];
    #pragma unroll
    for (int j = 0; j < 4; j++)
        h[j] = __floats2half2_rn(v[2 * j] * inv, v[2 * j + 1] * inv);
    *(uint4*)(orow + t * 8) = *(uint4*)h;
}

// ---------------------------------------------------------------------------
// Launch sequence (graph-capturable; no sync, no alloc)
// ---------------------------------------------------------------------------
extern "C" void kernel_launch(void* const* d_in, const int* in_sizes, int n_in,
                              void* d_out, int out_size)
{
    const float* Q  = (const float*)d_in[0];
    const float* K  = (const float*)d_in[1];
    const float* V  = (const float*)d_in[2];
    const float* Wr = (const float*)d_in[3];
    const float* Wq = (const float*)d_in[4];
    const float* Wk = (const float*)d_in[5];
    const float* Wv = (const float*)d_in[6];
    float* out = (float*)d_out;

    __half *pWf, *pqkv, *pvT, *pPh;
    float* pP;
    cudaGetSymbolAddress((void**)&pWf,   g_Wf);
    cudaGetSymbolAddress((void**)&pqkv,  g_qkv);
    cudaGetSymbolAddress((void**)&pvT,   g_vT);
    cudaGetSymbolAddress((void**)&pP,    g_P);
    cudaGetSymbolAddress((void**)&pPh,   g_Ph);

    const long long sW  = (long long)LOWD * KDIM;
    const long long sQK = (long long)BATCH * SEQ * LOWD;   // q/k/v stride in g_qkv
    const long long sBS = (long long)SEQ * LOWD;           // per-batch q/k/v stride
    const float scale = 1.0f / sqrtf((float)LOWD);

    // 1) Fold weights (single fused launch over z): Wf[z] = W{q,k,v} @ Wr
    {
        dim3 grid(KDIM / 128, LOWD / 128, 3);
        fold_nn<<<grid, 256>>>(Wq, Wk, Wv, Wr, pWf, LOWD, LOWD, KDIM, KDIM, sW);
    }

    // 2) Projections (fused over z, fp32 A converted inline):
    //    qkv[z] = rn16(QKV[z]) @ Wf[z]^T  (fp16 out)
    {
        dim3 grid(LOWD / 128, (BATCH * SEQ) / 128, 3);
        hgemm_proj<<<grid, 256>>>(Q, K, V, pWf, pqkv, sW, sQK);
    }

    // 3) vT for the NT AV GEMM
    {
        dim3 grid(LOWD / 32, SEQ / 32, BATCH);
        transpose_v<<<grid, dim3(32, 8)>>>(pqkv + 2 * sQK, pvT);
    }

    // 4) Scores: P[b] = scale * q[b] @ k[b]^T  (fp32 out)
    {
        dim3 grid(SEQ / 128, SEQ / 128, BATCH);
        hgemm_nt<false><<<grid, 256>>>(
            pqkv, pqkv + sQK, pP, LOWD, LOWD, LOWD, SEQ,
            sBS, sBS, (long long)SEQ * SEQ, scale);
    }

    // 5) Softmax: fp32 scores -> fp16 probs
    softmax_h<<<BATCH * SEQ, 256>>>(pP, pPh);

    // 6) AV: out[b] = Ph[b] @ vT[b]^T  (fp32 out)
    {
        dim3 grid(LOWD / 128, SEQ / 128, BATCH);
        hgemm_nt<false><<<grid, 256>>>(
            pPh, pvT, out, SEQ, SEQ, SEQ, LOWD,
            (long long)SEQ * SEQ, sBS, sBS, 1.0f);
    }
}